// round 9
// baseline (speedup 1.0000x reference)
#include <cuda_runtime.h>
#include <cuda_bf16.h>

#define NLAGS   250
#define LPAD    256
#define TILE_J  512
#define NBLOCKS 444          // 3 CTAs/SM * 148 SMs
#define THREADS 256
#define GLOG    768          // logical g floats per tile (TILE_J + 256 halo)
#define GPAD    1152         // phys floats: i + 4*(i>>3)

typedef unsigned long long ull;

// Deterministic reduction scratch (no allocs allowed)
__device__ float  g_partialT[LPAD * NBLOCKS];   // transposed: lag-major, contiguous per lag
__device__ float4 g_sums4[NBLOCKS];
__device__ float  g_cross[LPAD];
__device__ float4 g_tot;

static __device__ __forceinline__ ull pk2(float lo, float hi) {
    ull r; asm("mov.b64 %0, {%1, %2};" : "=l"(r) : "f"(lo), "f"(hi)); return r;
}
static __device__ __forceinline__ void ffma2(ull& d, ull a, ull b) {
    asm("fma.rn.f32x2 %0, %1, %2, %0;" : "+l"(d) : "l"(a), "l"(b));
}
static __device__ __forceinline__ float2 unpk(ull v) {
    float lo, hi; asm("mov.b64 {%0, %1}, %2;" : "=f"(lo), "=f"(hi) : "l"(v));
    return make_float2(lo, hi);
}

// ---------------------------------------------------------------------------
// Kernel A: per-block partial cross-correlations for 256 lags + partial sums.
// Each warp handles 64 j's per tile (8 batches of 8); each lane owns 8
// consecutive lags, packed as 4 f32x2 accumulators (lags 2k',2k'+1).
// g stored with 4-per-8 padding: phys = i + 4*(i>>3) -> conflict-free LDS.128.
// p stored duplicated (p,p) so broadcast pairs load directly as ulonglong2.
// ---------------------------------------------------------------------------
__global__ void __launch_bounds__(THREADS, 3) cccorr_kernel(const float* __restrict__ p,
                                                            const float* __restrict__ g,
                                                            int T) {
    __shared__ __align__(16) float p2_s[2 * TILE_J];
    __shared__ __align__(16) float g_s[GPAD];
    __shared__ float red[8 * LPAD];

    const int tid    = threadIdx.x;
    const int lane   = tid & 31;
    const int warpId = tid >> 5;
    const int jj0    = warpId * 64;    // warp's j sub-slice within tile
    const int n0     = lane * 8;       // lane's base lag

    ull acc2[4] = {0ull, 0ull, 0ull, 0ull};   // bits of (0.f,0.f) == 0
    float sp = 0.f, sp2 = 0.f, sg = 0.f, sg2 = 0.f;

    const float4*     gq = (const float4*)g_s;
    const ulonglong2* pp = (const ulonglong2*)p2_s;
    const int f0  = 3 * ((jj0 + n0) >> 3);   // f4 base of this lane's window
    const int pq0 = jj0 >> 1;                // ulonglong2 base of warp's p pairs

    const int ntiles = (T + TILE_J - 1) / TILE_J;
    for (int tile = blockIdx.x; tile < ntiles; tile += NBLOCKS) {
        const int base = tile * TILE_J;

        // Load p tile duplicated (zero-padded) + accumulate sums
        for (int i = tid; i < TILE_J; i += THREADS) {
            int gi = base + i;
            float v = (gi < T) ? p[gi] : 0.f;
            p2_s[2 * i]     = v;
            p2_s[2 * i + 1] = v;
            sp += v; sp2 += v * v;
        }
        // Load g tile + halo, padded phys = i + 4*(i>>3), zero past T
        for (int i = tid; i < GLOG; i += THREADS) {
            int gi = base + i;
            float v = (gi < T) ? g[gi] : 0.f;
            g_s[i + ((i >> 3) << 2)] = v;
            if (i < TILE_J) { sg += v; sg2 += v * v; }
        }
        __syncthreads();

        // 8 batches of 8 j's; window s[0..15] from 4 quads; E/O = even/odd pairs
#pragma unroll 1
        for (int u = 0; u < 8; u++) {
            const int qb = f0 + 3 * u;
            float4 Q0 = gq[qb], Q1 = gq[qb + 1], Q2 = gq[qb + 3], Q3 = gq[qb + 4];
            const float s[16] = {Q0.x, Q0.y, Q0.z, Q0.w, Q1.x, Q1.y, Q1.z, Q1.w,
                                 Q2.x, Q2.y, Q2.z, Q2.w, Q3.x, Q3.y, Q3.z, Q3.w};
            ull E[7], O[7];
#pragma unroll
            for (int m = 0; m < 7; m++) {
                E[m] = pk2(s[2 * m],     s[2 * m + 1]);
                O[m] = pk2(s[2 * m + 1], s[2 * m + 2]);
            }
            ulonglong2 P0 = pp[pq0 + 4 * u],     P1 = pp[pq0 + 4 * u + 1];
            ulonglong2 P2 = pp[pq0 + 4 * u + 2], P3 = pp[pq0 + 4 * u + 3];
            const ull pv[8] = {P0.x, P0.y, P1.x, P1.y, P2.x, P2.y, P3.x, P3.y};
#pragma unroll
            for (int j = 0; j < 8; j += 2) {
                const int m0 = j >> 1;
                ffma2(acc2[0], pv[j], E[m0]);
                ffma2(acc2[1], pv[j], E[m0 + 1]);
                ffma2(acc2[2], pv[j], E[m0 + 2]);
                ffma2(acc2[3], pv[j], E[m0 + 3]);
                ffma2(acc2[0], pv[j + 1], O[m0]);
                ffma2(acc2[1], pv[j + 1], O[m0 + 1]);
                ffma2(acc2[2], pv[j + 1], O[m0 + 2]);
                ffma2(acc2[3], pv[j + 1], O[m0 + 3]);
            }
        }
        __syncthreads();
    }

    // Unpack + reduce 8 warps' partials per lag -> one row per block (transposed)
#pragma unroll
    for (int k = 0; k < 4; k++) {
        float2 v = unpk(acc2[k]);
        red[warpId * LPAD + n0 + 2 * k]     = v.x;
        red[warpId * LPAD + n0 + 2 * k + 1] = v.y;
    }
    __syncthreads();
    {
        float s = 0.f;
#pragma unroll
        for (int w = 0; w < 8; w++) s += red[w * LPAD + tid];
        g_partialT[tid * NBLOCKS + blockIdx.x] = s;
    }

    // Reduce the 4 scalar sums
#pragma unroll
    for (int off = 16; off; off >>= 1) {
        sp  += __shfl_down_sync(0xFFFFFFFFu, sp,  off);
        sp2 += __shfl_down_sync(0xFFFFFFFFu, sp2, off);
        sg  += __shfl_down_sync(0xFFFFFFFFu, sg,  off);
        sg2 += __shfl_down_sync(0xFFFFFFFFu, sg2, off);
    }
    __shared__ float sred[8][4];
    if (lane == 0) {
        sred[warpId][0] = sp;  sred[warpId][1] = sp2;
        sred[warpId][2] = sg;  sred[warpId][3] = sg2;
    }
    __syncthreads();
    if (tid < 4) {
        float t = 0.f;
#pragma unroll
        for (int w = 0; w < 8; w++) t += sred[w][tid];
        ((float*)&g_sums4[blockIdx.x])[tid] = t;
    }
}

// ---------------------------------------------------------------------------
// Kernel B1: grid-parallel reduction. Blocks 0..249 reduce one lag each
// (444 contiguous floats, coalesced). Block 250 reduces the float4 sums.
// ---------------------------------------------------------------------------
#define B1_THREADS 128

__global__ void __launch_bounds__(B1_THREADS) reduce_kernel() {
    const int t    = threadIdx.x;
    const int lane = t & 31;
    const int wp   = t >> 5;
    const int lag  = blockIdx.x;

    if (lag < NLAGS) {
        const float* base = g_partialT + lag * NBLOCKS;
        float s = base[t] + base[t + B1_THREADS] + base[t + 2 * B1_THREADS];  // 384
        if (t < NBLOCKS - 3 * B1_THREADS) s += base[3 * B1_THREADS + t];      // +60
#pragma unroll
        for (int off = 16; off; off >>= 1) s += __shfl_down_sync(0xFFFFFFFFu, s, off);
        __shared__ float ws[4];
        if (lane == 0) ws[wp] = s;
        __syncthreads();
        if (t == 0) g_cross[lag] = (ws[0] + ws[1]) + (ws[2] + ws[3]);
    } else {
        // block 250: reduce g_sums4
        float x = 0.f, y = 0.f, z = 0.f, w = 0.f;
        for (int i = t; i < NBLOCKS; i += B1_THREADS) {
            float4 v = g_sums4[i];
            x += v.x; y += v.y; z += v.z; w += v.w;
        }
#pragma unroll
        for (int off = 16; off; off >>= 1) {
            x += __shfl_down_sync(0xFFFFFFFFu, x, off);
            y += __shfl_down_sync(0xFFFFFFFFu, y, off);
            z += __shfl_down_sync(0xFFFFFFFFu, z, off);
            w += __shfl_down_sync(0xFFFFFFFFu, w, off);
        }
        __shared__ float4 ws4[4];
        if (lane == 0) ws4[wp] = make_float4(x, y, z, w);
        __syncthreads();
        if (t == 0) {
            float4 a = ws4[0], b = ws4[1], c = ws4[2], d = ws4[3];
            g_tot = make_float4((a.x + b.x) + (c.x + d.x),
                                (a.y + b.y) + (c.y + d.y),
                                (a.z + b.z) + (c.z + d.z),
                                (a.w + b.w) + (c.w + d.w));
        }
    }
}

// ---------------------------------------------------------------------------
// Kernel B2: tiny finalize. Tail scan + per-lag CCC + scalar output.
// ---------------------------------------------------------------------------
__global__ void __launch_bounds__(LPAD) finalize_kernel(const float* __restrict__ p,
                                                        int T,
                                                        float* __restrict__ out) {
    __shared__ float scanA[LPAD], scanB[LPAD];
    __shared__ float scan2A[LPAD], scan2B[LPAD];
    __shared__ float cccs[LPAD];

    const int tid = threadIdx.x;

    // Tail values + Hillis-Steele inclusive scan (8 steps)
    {
        float v = (tid >= 1) ? p[T - tid] : 0.f;
        scanA[tid]  = v;
        scan2A[tid] = v * v;
    }
    __syncthreads();
#pragma unroll
    for (int s = 0; s < 8; s++) {
        int off = 1 << s;
        float a  = scanA[tid]  + ((tid >= off) ? scanA[tid - off]  : 0.f);
        float a2 = scan2A[tid] + ((tid >= off) ? scan2A[tid - off] : 0.f);
        __syncthreads();
        scanB[tid] = a; scan2B[tid] = a2;
        __syncthreads();
        scanA[tid] = scanB[tid]; scan2A[tid] = scan2B[tid];
        __syncthreads();
    }

    const float4 tot = g_tot;
    const float Sp  = tot.x, Sp2 = tot.y;
    const float Sg  = tot.z, Sg2 = tot.w;
    const float Tf  = (float)T;
    const float mean_gt = Sg / Tf;
    const float var_gt  = (Sg2 - Tf * mean_gt * mean_gt) / (Tf - 1.f);

    float ccc = 0.f;
    if (tid < NLAGS) {
        float cross = g_cross[tid];
        float Spn   = Sp  - scanA[tid];     // sum of p[0 : T-n]
        float Spn2  = Sp2 - scan2A[tid];
        float mean_pred = Spn / Tf;
        float var_pred  = (Spn2 - Tf * mean_pred * mean_pred) / (Tf - 1.f);
        float cov = (cross - mean_gt * Spn) / Tf;   // population covariance
        float dm  = mean_gt - mean_pred;
        float denom = var_gt + var_pred + dm * dm;
        ccc = 2.f * cov / denom;
    }
    cccs[tid] = ccc;
    __syncthreads();
#pragma unroll
    for (int off = LPAD / 2; off >= 1; off >>= 1) {
        if (tid < off) cccs[tid] += cccs[tid + off];
        __syncthreads();
    }
    if (tid == 0) out[0] = 1.f - cccs[0] / (float)NLAGS;
}

extern "C" void kernel_launch(void* const* d_in, const int* in_sizes, int n_in,
                              void* d_out, int out_size) {
    const float* pred = (const float*)d_in[0];
    const float* gt   = (const float*)d_in[1];
    float* out = (float*)d_out;
    int T = in_sizes[0];

    cccorr_kernel<<<NBLOCKS, THREADS>>>(pred, gt, T);
    reduce_kernel<<<NLAGS + 1, B1_THREADS>>>();
    finalize_kernel<<<1, LPAD>>>(pred, T, out);
}

// round 12
// speedup vs baseline: 1.0843x; 1.0843x over previous
#include <cuda_runtime.h>
#include <cuda_bf16.h>

#define NLAGS   250
#define LPAD    256
#define NBLOCKS 444          // 3 CTAs/SM * 148 SMs
#define THREADS 256
#define HALF    192          // half-chunk; chunk = 2*HALF j's
#define CHUNK   (2 * HALF)   // 384
#define GG_LOG  (HALF + 256) // 448 logical float2 pairs (window needs up to 447)
#define GG_PHYS (GG_LOG + GG_LOG / 8)   // 504 with 1-per-8 padding

typedef unsigned long long ull;

// Deterministic reduction scratch (no allocs allowed)
__device__ float  g_partialT[LPAD * NBLOCKS];   // transposed: lag-major, contiguous per lag
__device__ float4 g_sums4[NBLOCKS];
__device__ float  g_cross[LPAD];
__device__ float4 g_tot;

static __device__ __forceinline__ void ffma2(ull& d, ull a, ull b) {
    asm("fma.rn.f32x2 %0, %1, %2, %0;" : "+l"(d) : "l"(a), "l"(b));
}
static __device__ __forceinline__ float2 unpk(ull v) {
    float lo, hi; asm("mov.b64 {%0, %1}, %2;" : "=f"(lo), "=f"(hi) : "l"(v));
    return make_float2(lo, hi);
}

// ---------------------------------------------------------------------------
// Kernel A: each block owns an exact j-range [r0,r1) (balanced to +/-1 j),
// processed in 384-j chunks split into lo/hi halves of 192.
// smem holds interleaved PAIRS: pp2[i]=(p[j],p[j+H]), gg2[i]=(g[x],g[x+H]);
// one FFMA2 accumulates lag k over both halves -> no pack instructions.
// Window LDS.64 conflict-free via 1-per-8 float2 padding (72B lane stride).
// ---------------------------------------------------------------------------
__global__ void __launch_bounds__(THREADS, 3) cccorr_kernel(const float* __restrict__ p,
                                                            const float* __restrict__ g,
                                                            int T) {
    __shared__ __align__(16) float2 pp2_s[HALF];
    __shared__ __align__(16) float2 gg2_s[GG_PHYS];
    __shared__ float red[8 * LPAD];

    const int tid    = threadIdx.x;
    const int lane   = tid & 31;
    const int warpId = tid >> 5;
    const int sw     = warpId * (HALF / 8);   // warp's step base (24 steps/warp)
    const int n0     = lane * 8;              // lane's base lag

    ull acc2[8];
#pragma unroll
    for (int k = 0; k < 8; k++) acc2[k] = 0ull;
    float sp = 0.f, sp2 = 0.f, sg = 0.f, sg2 = 0.f;

    const ull*        ggu = (const ull*)gg2_s;
    const ulonglong2* ppq = (const ulonglong2*)pp2_s;

    // Exact balanced j-range for this block
    const long long Tll = T;
    const int r0 = (int)((Tll * blockIdx.x) / NBLOCKS);
    const int r1 = (int)((Tll * (blockIdx.x + 1)) / NBLOCKS);

    for (int c0 = r0; c0 < r1; c0 += CHUNK) {
        // Load p pairs (zero outside [c0, r1)) + accumulate sums
        for (int i = tid; i < HALF; i += THREADS) {
            int jl = c0 + i, jh = jl + HALF;
            float a = (jl < r1) ? p[jl] : 0.f;
            float b = (jh < r1) ? p[jh] : 0.f;
            pp2_s[i] = make_float2(a, b);
            sp += a + b; sp2 += a * a + b * b;
        }
        // Load g pairs + halo (zero past T); sums gated to x in [c0, r1)
        for (int i = tid; i < GG_LOG; i += THREADS) {
            int xl = c0 + i, xh = xl + HALF;
            float a = (xl < T) ? g[xl] : 0.f;
            float b = (xh < T) ? g[xh] : 0.f;
            gg2_s[i + (i >> 3)] = make_float2(a, b);
            if (i < HALF) {
                if (xl < r1) { sg += a; sg2 += a * a; }
                if (xh < r1) { sg += b; sg2 += b * b; }
            }
        }
        __syncthreads();

        // 3 groups of 8 steps; per group: 64 FFMA2, 16 LDS.64, 4 bcast LDS.128
#pragma unroll
        for (int q = 0; q < 3; q++) {
            const int sb = sw + 8 * q;
            const int i0 = sb + n0;                    // multiple of 8
            const ull* wb = ggu + i0 + (i0 >> 3);
            ull W[16];
#pragma unroll
            for (int k = 0; k < 8; k++)  W[k] = wb[k];
#pragma unroll
            for (int k = 8; k < 16; k++) W[k] = wb[k + 1];
#pragma unroll
            for (int j = 0; j < 8; j += 2) {
                ulonglong2 P = ppq[(sb + j) >> 1];     // warp-uniform broadcast
#pragma unroll
                for (int k = 0; k < 8; k++) ffma2(acc2[k], P.x, W[j + k]);
#pragma unroll
                for (int k = 0; k < 8; k++) ffma2(acc2[k], P.y, W[j + 1 + k]);
            }
        }
        __syncthreads();
    }

    // Unpack (lo+hi = both halves) + reduce 8 warps per lag -> transposed partials
#pragma unroll
    for (int k = 0; k < 8; k++) {
        float2 v = unpk(acc2[k]);
        red[warpId * LPAD + n0 + k] = v.x + v.y;
    }
    __syncthreads();
    {
        float s = 0.f;
#pragma unroll
        for (int w = 0; w < 8; w++) s += red[w * LPAD + tid];
        g_partialT[tid * NBLOCKS + blockIdx.x] = s;
    }

    // Reduce the 4 scalar sums
#pragma unroll
    for (int off = 16; off; off >>= 1) {
        sp  += __shfl_down_sync(0xFFFFFFFFu, sp,  off);
        sp2 += __shfl_down_sync(0xFFFFFFFFu, sp2, off);
        sg  += __shfl_down_sync(0xFFFFFFFFu, sg,  off);
        sg2 += __shfl_down_sync(0xFFFFFFFFu, sg2, off);
    }
    __shared__ float sred[8][4];
    if (lane == 0) {
        sred[warpId][0] = sp;  sred[warpId][1] = sp2;
        sred[warpId][2] = sg;  sred[warpId][3] = sg2;
    }
    __syncthreads();
    if (tid < 4) {
        float t = 0.f;
#pragma unroll
        for (int w = 0; w < 8; w++) t += sred[w][tid];
        ((float*)&g_sums4[blockIdx.x])[tid] = t;
    }
}

// ---------------------------------------------------------------------------
// Kernel B1: grid-parallel reduction. Blocks 0..249 reduce one lag each
// (444 contiguous floats, coalesced). Block 250 reduces the float4 sums.
// ---------------------------------------------------------------------------
#define B1_THREADS 128

__global__ void __launch_bounds__(B1_THREADS) reduce_kernel() {
    const int t    = threadIdx.x;
    const int lane = t & 31;
    const int wp   = t >> 5;
    const int lag  = blockIdx.x;

    if (lag < NLAGS) {
        const float* base = g_partialT + lag * NBLOCKS;
        float s = base[t] + base[t + B1_THREADS] + base[t + 2 * B1_THREADS];  // 384
        if (t < NBLOCKS - 3 * B1_THREADS) s += base[3 * B1_THREADS + t];      // +60
#pragma unroll
        for (int off = 16; off; off >>= 1) s += __shfl_down_sync(0xFFFFFFFFu, s, off);
        __shared__ float ws[4];
        if (lane == 0) ws[wp] = s;
        __syncthreads();
        if (t == 0) g_cross[lag] = (ws[0] + ws[1]) + (ws[2] + ws[3]);
    } else {
        // block 250: reduce g_sums4
        float x = 0.f, y = 0.f, z = 0.f, w = 0.f;
        for (int i = t; i < NBLOCKS; i += B1_THREADS) {
            float4 v = g_sums4[i];
            x += v.x; y += v.y; z += v.z; w += v.w;
        }
#pragma unroll
        for (int off = 16; off; off >>= 1) {
            x += __shfl_down_sync(0xFFFFFFFFu, x, off);
            y += __shfl_down_sync(0xFFFFFFFFu, y, off);
            z += __shfl_down_sync(0xFFFFFFFFu, z, off);
            w += __shfl_down_sync(0xFFFFFFFFu, w, off);
        }
        __shared__ float4 ws4[4];
        if (lane == 0) ws4[wp] = make_float4(x, y, z, w);
        __syncthreads();
        if (t == 0) {
            float4 a = ws4[0], b = ws4[1], c = ws4[2], d = ws4[3];
            g_tot = make_float4((a.x + b.x) + (c.x + d.x),
                                (a.y + b.y) + (c.y + d.y),
                                (a.z + b.z) + (c.z + d.z),
                                (a.w + b.w) + (c.w + d.w));
        }
    }
}

// ---------------------------------------------------------------------------
// Kernel B2: tiny finalize. Tail scan + per-lag CCC + scalar output.
// ---------------------------------------------------------------------------
__global__ void __launch_bounds__(LPAD) finalize_kernel(const float* __restrict__ p,
                                                        int T,
                                                        float* __restrict__ out) {
    __shared__ float scanA[LPAD], scanB[LPAD];
    __shared__ float scan2A[LPAD], scan2B[LPAD];
    __shared__ float cccs[LPAD];

    const int tid = threadIdx.x;

    // Tail values + Hillis-Steele inclusive scan (8 steps)
    {
        float v = (tid >= 1) ? p[T - tid] : 0.f;
        scanA[tid]  = v;
        scan2A[tid] = v * v;
    }
    __syncthreads();
#pragma unroll
    for (int s = 0; s < 8; s++) {
        int off = 1 << s;
        float a  = scanA[tid]  + ((tid >= off) ? scanA[tid - off]  : 0.f);
        float a2 = scan2A[tid] + ((tid >= off) ? scan2A[tid - off] : 0.f);
        __syncthreads();
        scanB[tid] = a; scan2B[tid] = a2;
        __syncthreads();
        scanA[tid] = scanB[tid]; scan2A[tid] = scan2B[tid];
        __syncthreads();
    }

    const float4 tot = g_tot;
    const float Sp  = tot.x, Sp2 = tot.y;
    const float Sg  = tot.z, Sg2 = tot.w;
    const float Tf  = (float)T;
    const float mean_gt = Sg / Tf;
    const float var_gt  = (Sg2 - Tf * mean_gt * mean_gt) / (Tf - 1.f);

    float ccc = 0.f;
    if (tid < NLAGS) {
        float cross = g_cross[tid];
        float Spn   = Sp  - scanA[tid];     // sum of p[0 : T-n]
        float Spn2  = Sp2 - scan2A[tid];
        float mean_pred = Spn / Tf;
        float var_pred  = (Spn2 - Tf * mean_pred * mean_pred) / (Tf - 1.f);
        float cov = (cross - mean_gt * Spn) / Tf;   // population covariance
        float dm  = mean_gt - mean_pred;
        float denom = var_gt + var_pred + dm * dm;
        ccc = 2.f * cov / denom;
    }
    cccs[tid] = ccc;
    __syncthreads();
#pragma unroll
    for (int off = LPAD / 2; off >= 1; off >>= 1) {
        if (tid < off) cccs[tid] += cccs[tid + off];
        __syncthreads();
    }
    if (tid == 0) out[0] = 1.f - cccs[0] / (float)NLAGS;
}

extern "C" void kernel_launch(void* const* d_in, const int* in_sizes, int n_in,
                              void* d_out, int out_size) {
    const float* pred = (const float*)d_in[0];
    const float* gt   = (const float*)d_in[1];
    float* out = (float*)d_out;
    int T = in_sizes[0];

    cccorr_kernel<<<NBLOCKS, THREADS>>>(pred, gt, T);
    reduce_kernel<<<NLAGS + 1, B1_THREADS>>>();
    finalize_kernel<<<1, LPAD>>>(pred, T, out);
}